// round 1
// baseline (speedup 1.0000x reference)
#include <cuda_runtime.h>

#define N_PTS   65536
#define M_CENT  2048
#define KNN     32
#define IN_DIM  40
#define H1D     64
#define H2D     128
#define OUTD    128
#define NROWS   (M_CENT*KNN)   // 65536

// ---------------- scratch (device globals; no allocation allowed) ----------------
__device__ float  g_h1[NROWS*H1D];      // 16 MB
__device__ float  g_h2[NROWS*H2D];      // 32 MB
__device__ float2 g_rel[NROWS];         // 512 KB
__device__ float2 g_cent[M_CENT];
__device__ float  g_s1[H1D], g_ss1[H1D], g_s2[H2D], g_ss2[H2D];

// ---------------- helpers ----------------
__device__ __forceinline__ unsigned smem_u32(const void* p) {
    return (unsigned)__cvta_generic_to_shared(p);
}
__device__ __forceinline__ unsigned mapa_rank(unsigned laddr, unsigned r) {
    unsigned a;
    asm("mapa.shared::cluster.u32 %0, %1, %2;" : "=r"(a) : "r"(laddr), "r"(r));
    return a;
}

// ---------------- init: zero BN accumulators (graph replays!) ----------------
__global__ void k_init() {
    int t = threadIdx.x;
    if (t < H1D) { g_s1[t] = 0.f; g_ss1[t] = 0.f; }
    if (t < H2D) { g_s2[t] = 0.f; g_ss2[t] = 0.f; }
}

// ---------------- FPS: 8-CTA cluster, all state in registers ----------------
#define FPS_C 8
#define FPS_T 512
#define FPS_PPT (N_PTS/(FPS_C*FPS_T))   // 16

__global__ void __cluster_dims__(FPS_C,1,1) __launch_bounds__(FPS_T,1)
k_fps(const float2* __restrict__ pts, float* __restrict__ cent_dout, int write_dout)
{
    __shared__ unsigned long long s_wk[FPS_T/32];
    __shared__ unsigned long long s_ck[2][FPS_C];
    __shared__ float s_cx, s_cy;
    __shared__ int   s_ci;

    unsigned rank; asm("mov.u32 %0, %%cluster_ctarank;" : "=r"(rank));
    int tid  = threadIdx.x;
    int base = ((int)rank * FPS_T + tid) * FPS_PPT;

    float px[FPS_PPT], py[FPS_PPT], d2[FPS_PPT];
    #pragma unroll
    for (int j = 0; j < FPS_PPT; j++) {
        float2 p = pts[base + j];
        px[j] = p.x; py[j] = p.y;
        d2[j] = __int_as_float(0x7f800000);   // +inf
    }

    float2 p0 = pts[0];
    float cx = p0.x, cy = p0.y;
    int   ci = 0;
    if (rank == 0 && tid == 0) {
        g_cent[0] = p0;
        if (write_dout) { cent_dout[0] = p0.x; cent_dout[1] = p0.y; }
    }

    for (int s = 1; s < M_CENT; s++) {
        // zero dist of previously-selected point (reference: dist.at[nxt].set(0))
        #pragma unroll
        for (int j = 0; j < FPS_PPT; j++)
            if (base + j == ci) d2[j] = 0.0f;

        float bm = -1.0f; int bi = base;
        #pragma unroll
        for (int j = 0; j < FPS_PPT; j++) {
            float dx = __fsub_rn(px[j], cx), dy = __fsub_rn(py[j], cy);
            float dd = __fadd_rn(__fmul_rn(dx,dx), __fmul_rn(dy,dy));
            float nd = fminf(d2[j], dd);
            d2[j] = nd;
            if (nd > bm) { bm = nd; bi = base + j; }   // strict > keeps smallest idx
        }
        // map to reference's dist domain exactly: sqrt(d2 + 1e-12)
        float sv = sqrtf(__fadd_rn(bm, 1e-12f));
        unsigned long long key =
            ((unsigned long long)__float_as_uint(sv) << 32) |
            (unsigned)(0xFFFFFFFFu - (unsigned)bi);    // larger key = smaller idx at ties

        #pragma unroll
        for (int off = 16; off; off >>= 1) {
            unsigned long long o = __shfl_down_sync(0xFFFFFFFFu, key, off);
            if (o > key) key = o;
        }
        if ((tid & 31) == 0) s_wk[tid >> 5] = key;
        __syncthreads();
        if (tid < 32) {
            unsigned long long k2 = (tid < (FPS_T/32)) ? s_wk[tid] : 0ull;
            #pragma unroll
            for (int off = 8; off; off >>= 1) {
                unsigned long long o = __shfl_down_sync(0xFFFFFFFFu, k2, off);
                if (o > k2) k2 = o;
            }
            if (tid == 0) {
                unsigned la = smem_u32(&s_ck[s & 1][rank]);
                unsigned ra = mapa_rank(la, 0);   // CTA0's copy of this slot
                asm volatile("st.shared::cluster.u64 [%0], %1;"
                             :: "r"(ra), "l"(k2) : "memory");
            }
        }
        asm volatile("barrier.cluster.arrive.aligned;" ::: "memory");
        asm volatile("barrier.cluster.wait.aligned;"   ::: "memory");

        if (tid == 0) {
            unsigned long long best = 0ull;
            #pragma unroll
            for (int c = 0; c < FPS_C; c++) {
                unsigned la = smem_u32(&s_ck[s & 1][c]);
                unsigned ra = mapa_rank(la, 0);
                unsigned long long k;
                asm volatile("ld.shared::cluster.u64 %0, [%1];"
                             : "=l"(k) : "r"(ra) : "memory");
                if (k > best) best = k;
            }
            int widx = (int)(0xFFFFFFFFu - (unsigned)best);
            float2 wp = pts[widx];
            s_cx = wp.x; s_cy = wp.y; s_ci = widx;
            if (rank == 0) {
                g_cent[s] = wp;
                if (write_dout) { cent_dout[2*s] = wp.x; cent_dout[2*s+1] = wp.y; }
            }
        }
        __syncthreads();
        cx = s_cx; cy = s_cy; ci = s_ci;
    }
}

// ---------------- ball query: 1 warp / centroid, first-K by index ----------------
__global__ __launch_bounds__(1024) void k_ballquery(const float2* __restrict__ pts)
{
    int gw   = (blockIdx.x * blockDim.x + threadIdx.x) >> 5;
    int lane = threadIdx.x & 31;
    if (gw >= M_CENT) return;

    float2 c  = g_cent[gw];
    float  c2 = __fadd_rn(__fmul_rn(c.x,c.x), __fmul_rn(c.y,c.y));

    int   cnt  = 0;
    bool  have = false;
    float fx = 0.f, fy = 0.f;

    for (int b = 0; b < N_PTS; b += 32) {
        float2 p   = pts[b + lane];
        float  p2  = __fadd_rn(__fmul_rn(p.x,p.x), __fmul_rn(p.y,p.y));
        float  dot = __fadd_rn(__fmul_rn(c.x,p.x), __fmul_rn(c.y,p.y));
        // reference formula: c2 + p2 - 2*(c·p)
        float  dd  = __fsub_rn(__fadd_rn(c2, p2), __fmul_rn(2.0f, dot));
        bool hit = (dd <= 0.0025f);
        unsigned m = __ballot_sync(0xFFFFFFFFu, hit);
        float rx = __fsub_rn(p.x, c.x), ry = __fsub_rn(p.y, c.y);
        if (!have && m) {
            int src = __ffs(m) - 1;
            fx = __shfl_sync(0xFFFFFFFFu, rx, src);
            fy = __shfl_sync(0xFFFFFFFFu, ry, src);
            have = true;
        }
        int pos = cnt + __popc(m & ((1u << lane) - 1u));
        if (hit && pos < KNN) g_rel[gw*KNN + pos] = make_float2(rx, ry);
        cnt += __popc(m);
        if (cnt >= KNN) break;
    }
    // pad with first hit (centroid itself always qualifies, so have==true)
    for (int s2 = cnt + lane; s2 < KNN; s2 += 32)
        g_rel[gw*KNN + s2] = make_float2(fx, fy);
}

// ---------------- layer1: freq-encode + [65536x40]@[40x64] + b1 ----------------
__global__ __launch_bounds__(128) void k_layer1(const float* __restrict__ W1,
                                                const float* __restrict__ b1)
{
    __shared__ float ws[IN_DIM*H1D];   // 10 KB
    __shared__ float bs[H1D];
    int tid = threadIdx.x;
    for (int i = tid; i < IN_DIM*H1D; i += 128) ws[i] = W1[i];
    if (tid < H1D) bs[tid] = b1[tid];
    __syncthreads();

    int r = blockIdx.x * 128 + tid;
    float2 q = g_rel[r];

    float acc[H1D];
    #pragma unroll
    for (int j = 0; j < H1D; j++) acc[j] = bs[j];

    for (int f = 0; f < 10; f++) {
        float fr = 3.14159265358979f * (float)(1 << f);
        float e0, e1, e2, e3;
        sincosf(__fmul_rn(q.x, fr), &e0, &e1);   // sin, cos of x
        sincosf(__fmul_rn(q.y, fr), &e2, &e3);   // sin, cos of y
        const float* w0 = &ws[(4*f + 0)*H1D];
        const float* w1 = &ws[(4*f + 1)*H1D];
        const float* w2 = &ws[(4*f + 2)*H1D];
        const float* w3 = &ws[(4*f + 3)*H1D];
        #pragma unroll
        for (int j = 0; j < H1D; j++) {
            acc[j] = fmaf(e0, w0[j], acc[j]);
            acc[j] = fmaf(e1, w1[j], acc[j]);
            acc[j] = fmaf(e2, w2[j], acc[j]);
            acc[j] = fmaf(e3, w3[j], acc[j]);
        }
    }
    float4* o = (float4*)&g_h1[(size_t)r * H1D];
    #pragma unroll
    for (int j = 0; j < H1D/4; j++)
        o[j] = make_float4(acc[4*j], acc[4*j+1], acc[4*j+2], acc[4*j+3]);
}

// ---------------- column sum / sumsq reduction ----------------
template <int C>
__device__ __forceinline__ void colreduce_body(const float* __restrict__ src,
                                               float* __restrict__ outs,
                                               float* __restrict__ outss)
{
    __shared__ float sh_s[256], sh_q[256];
    int tid = threadIdx.x;
    int col = tid & (C - 1);
    int sub = tid / C;
    const int L = 256 / C;
    int row0 = blockIdx.x * (NROWS / 256);   // 256 rows per block (grid=256)
    float s = 0.f, q = 0.f;
    for (int r = sub; r < NROWS/256; r += L) {
        float v = src[(size_t)(row0 + r) * C + col];
        s += v;
        q  = fmaf(v, v, q);
    }
    sh_s[tid] = s; sh_q[tid] = q;
    __syncthreads();
    if (tid < C) {
        float ts = 0.f, tq = 0.f;
        #pragma unroll
        for (int u = 0; u < L; u++) { ts += sh_s[u*C + tid]; tq += sh_q[u*C + tid]; }
        atomicAdd(&outs[tid], ts);
        atomicAdd(&outss[tid], tq);
    }
}
__global__ __launch_bounds__(256) void k_red1() { colreduce_body<H1D>(g_h1, g_s1, g_ss1); }
__global__ __launch_bounds__(256) void k_red2() { colreduce_body<H2D>(g_h2, g_s2, g_ss2); }

// ---------------- layer2: BN1+ReLU then [65536x64]@[64x128] + b2 ----------------
__global__ __launch_bounds__(128) void k_layer2(const float* __restrict__ W2,
                                                const float* __restrict__ b2,
                                                const float* __restrict__ g1,
                                                const float* __restrict__ be1)
{
    __shared__ float xs[32*H1D];       // 8 KB
    __shared__ float sc[H1D], sh[H1D];
    int tid = threadIdx.x;
    if (tid < H1D) {
        float m  = g_s1[tid]  * (1.0f/NROWS);
        float v  = g_ss1[tid] * (1.0f/NROWS) - m*m;
        float rs = rsqrtf(v + 1e-5f);
        float scale = g1[tid] * rs;
        sc[tid] = scale;
        sh[tid] = be1[tid] - m * scale;
    }
    __syncthreads();

    int row0 = blockIdx.x * 32;
    for (int t = tid; t < 32*H1D; t += 128) {
        int c = t & (H1D - 1);
        float v = g_h1[(size_t)row0 * H1D + t];
        xs[t] = fmaxf(fmaf(v, sc[c], sh[c]), 0.0f);
    }
    __syncthreads();

    int j = tid;            // output column (128 cols)
    float acc[32];
    float bj = b2[j];
    #pragma unroll
    for (int r = 0; r < 32; r++) acc[r] = bj;
    for (int i = 0; i < H1D; i++) {
        float w = __ldg(&W2[i*H2D + j]);
        #pragma unroll
        for (int r = 0; r < 32; r++)
            acc[r] = fmaf(xs[r*H1D + i], w, acc[r]);
    }
    #pragma unroll
    for (int r = 0; r < 32; r++)
        g_h2[(size_t)(row0 + r) * H2D + j] = acc[r];
}

// ---------------- layer3: BN2+ReLU, [32x128]@[128x128]+b3, max over 32 ----------------
__global__ __launch_bounds__(128) void k_layer3(const float* __restrict__ W3,
                                                const float* __restrict__ b3,
                                                const float* __restrict__ g2,
                                                const float* __restrict__ be2,
                                                float* __restrict__ out)
{
    __shared__ float xs[32*H2D];       // 16 KB
    __shared__ float sc[H2D], sh[H2D];
    int tid = threadIdx.x;
    {
        float m  = g_s2[tid]  * (1.0f/NROWS);
        float v  = g_ss2[tid] * (1.0f/NROWS) - m*m;
        float rs = rsqrtf(v + 1e-5f);
        float scale = g2[tid] * rs;
        sc[tid] = scale;
        sh[tid] = be2[tid] - m * scale;
    }
    __syncthreads();

    int row0 = blockIdx.x * 32;        // one center per block
    for (int t = tid; t < 32*H2D; t += 128) {
        int c = t & (H2D - 1);
        float v = g_h2[(size_t)row0 * H2D + t];
        xs[t] = fmaxf(fmaf(v, sc[c], sh[c]), 0.0f);
    }
    __syncthreads();

    int j = tid;
    float acc[32];
    float bj = b3[j];
    #pragma unroll
    for (int r = 0; r < 32; r++) acc[r] = bj;
    for (int i = 0; i < H2D; i++) {
        float w = __ldg(&W3[i*OUTD + j]);
        #pragma unroll
        for (int r = 0; r < 32; r++)
            acc[r] = fmaf(xs[r*H2D + i], w, acc[r]);
    }
    float mv = acc[0];
    #pragma unroll
    for (int r = 1; r < 32; r++) mv = fmaxf(mv, acc[r]);
    out[(size_t)blockIdx.x * OUTD + j] = mv;
}

// ---------------- launch ----------------
extern "C" void kernel_launch(void* const* d_in, const int* in_sizes, int n_in,
                              void* d_out, int out_size)
{
    const float2* pts = (const float2*)d_in[0];
    const float* W1  = (const float*)d_in[1];
    const float* b1  = (const float*)d_in[2];
    const float* g1  = (const float*)d_in[3];
    const float* be1 = (const float*)d_in[4];
    const float* W2  = (const float*)d_in[5];
    const float* b2  = (const float*)d_in[6];
    const float* g2  = (const float*)d_in[7];
    const float* be2 = (const float*)d_in[8];
    const float* W3  = (const float*)d_in[9];
    const float* b3  = (const float*)d_in[10];

    float* out = (float*)d_out;
    float* cent_out = out + (size_t)M_CENT * OUTD;
    int wd = (out_size >= M_CENT*OUTD + M_CENT*2) ? 1 : 0;

    k_init<<<1, 128>>>();
    k_fps<<<FPS_C, FPS_T>>>(pts, cent_out, wd);
    k_ballquery<<<64, 1024>>>(pts);
    k_layer1<<<NROWS/128, 128>>>(W1, b1);
    k_red1<<<256, 256>>>();
    k_layer2<<<NROWS/32, 128>>>(W2, b2, g1, be1);
    k_red2<<<256, 256>>>();
    k_layer3<<<M_CENT, 128>>>(W3, b3, g2, be2, out);
}